// round 8
// baseline (speedup 1.0000x reference)
#include <cuda_runtime.h>
#include <cstdint>
#include <cstdio>

// ---------------- problem constants ----------------
#define Hdim   256
#define GD     16
#define GL     16
#define NLAY   2
#define NH     4
#define DH     64
#define CS     256
#define TOTAL  263168
#define NCH    1028
#define BATCH  16

// ---------------- device scratch (no allocation allowed) ----------------
__device__ float g_h[BATCH * GL * Hdim];
__device__ float g_qkv[BATCH * GL * 3 * Hdim];
__device__ float g_attn[BATCH * GL * Hdim];
__device__ float g_tmp[BATCH * GL * Hdim];
__device__ float g_ffn[BATCH * GL * 4 * Hdim];
__device__ float g_latent[BATCH * Hdim];
__device__ float g_wf[768 * 256];      // fused Wih @ Wo
__device__ float g_gia[17 * 768];      // rows 0..15: gi0 per batch; row 16: Wih·ob + bih

// =====================================================================
// Transformer preamble — dot products split into 4 partials (chain/4)
// =====================================================================

__global__ void embed_kernel(const float* __restrict__ g,
                             const float* __restrict__ W,
                             const float* __restrict__ bias,
                             float* __restrict__ h)
{
    int row = blockIdx.x;
    int j   = threadIdx.x;
    __shared__ float sg[GD];
    if (j < GD) sg[j] = g[row * GD + j];
    __syncthreads();
    float a = bias[j];
    const float* w = W + j * GD;
#pragma unroll
    for (int d = 0; d < GD; d++) a = fmaf(sg[d], w[d], a);
    h[row * Hdim + j] = a;
}

// block computes 4 input rows x NOUT outputs; 4 independent k-partials per row
template<int NOUT, int KD, bool RELU>
__global__ void gemm_rows4(const float* __restrict__ X,
                           const float* __restrict__ W,
                           const float* __restrict__ bias,
                           float* __restrict__ Y)
{
    __shared__ float sx[4 * KD];
    int j  = threadIdx.x;
    int r0 = blockIdx.x * 4;
    for (int i = j; i < 4 * KD; i += NOUT) sx[i] = X[r0 * KD + i];
    __syncthreads();
    const float* w = W + (size_t)j * KD;
    float acc[4][4];
#pragma unroll
    for (int rr = 0; rr < 4; rr++)
#pragma unroll
        for (int pp = 0; pp < 4; pp++) acc[rr][pp] = 0.f;
    constexpr int KQ = KD / 4;
#pragma unroll
    for (int pp = 0; pp < 4; pp++) {
        const float* wp = w + pp * KQ;
#pragma unroll 4
        for (int k = 0; k < KQ; k += 4) {
            float4 wv = *reinterpret_cast<const float4*>(wp + k);
#pragma unroll
            for (int rr = 0; rr < 4; rr++) {
                const float* sxr = sx + rr * KD + pp * KQ + k;
                acc[rr][pp] = fmaf(sxr[0], wv.x, acc[rr][pp]);
                acc[rr][pp] = fmaf(sxr[1], wv.y, acc[rr][pp]);
                acc[rr][pp] = fmaf(sxr[2], wv.z, acc[rr][pp]);
                acc[rr][pp] = fmaf(sxr[3], wv.w, acc[rr][pp]);
            }
        }
    }
    float bv = bias[j];
#pragma unroll
    for (int rr = 0; rr < 4; rr++) {
        float a = bv + ((acc[rr][0] + acc[rr][1]) + (acc[rr][2] + acc[rr][3]));
        if (RELU) a = fmaxf(a, 0.f);
        Y[(size_t)(r0 + rr) * NOUT + j] = a;
    }
}

__global__ void attn_kernel(const float* __restrict__ qkv,
                            float* __restrict__ obuf)
{
    int b    = blockIdx.x >> 2;
    int head = blockIdx.x & 3;
    __shared__ float sq[GL][DH], sk[GL][DH], sv[GL][DH], sa[GL][GL];
    int tid = threadIdx.x;
    for (int i = tid; i < GL * DH; i += 256) {
        int s_ = i >> 6, d = i & 63;
        int base = (b * GL + s_) * (3 * Hdim) + head * DH + d;
        sq[s_][d] = qkv[base];
        sk[s_][d] = qkv[base + Hdim];
        sv[s_][d] = qkv[base + 2 * Hdim];
    }
    __syncthreads();
    int s_ = tid >> 4, t_ = tid & 15;
    float p0 = 0.f, p1 = 0.f;
#pragma unroll
    for (int d = 0; d < DH; d += 2) {
        p0 = fmaf(sq[s_][d],     sk[t_][d],     p0);
        p1 = fmaf(sq[s_][d + 1], sk[t_][d + 1], p1);
    }
    float sc = (p0 + p1) * 0.125f;
    float mx = sc;
#pragma unroll
    for (int m = 8; m > 0; m >>= 1) mx = fmaxf(mx, __shfl_xor_sync(0xffffffffu, mx, m));
    float e = __expf(sc - mx);
    float sum = e;
#pragma unroll
    for (int m = 8; m > 0; m >>= 1) sum += __shfl_xor_sync(0xffffffffu, sum, m);
    sa[s_][t_] = e / sum;
    __syncthreads();
    int d4 = tid & 15; s_ = tid >> 4;
#pragma unroll
    for (int dd = 0; dd < 4; dd++) {
        int d = d4 * 4 + dd;
        float acc = 0.f;
#pragma unroll
        for (int t = 0; t < GL; t++) acc = fmaf(sa[s_][t], sv[t][d], acc);
        obuf[(b * GL + s_) * Hdim + head * DH + d] = acc;
    }
}

__global__ void addln_kernel(const float* __restrict__ y,
                             float* __restrict__ h,
                             const float* __restrict__ gamma,
                             const float* __restrict__ beta)
{
    int row = blockIdx.x;
    int j   = threadIdx.x;
    __shared__ float red[16];
    float v = y[row * Hdim + j] + h[row * Hdim + j];
    float s1 = v, s2 = v * v;
#pragma unroll
    for (int m = 16; m > 0; m >>= 1) {
        s1 += __shfl_xor_sync(0xffffffffu, s1, m);
        s2 += __shfl_xor_sync(0xffffffffu, s2, m);
    }
    int w = j >> 5;
    if ((j & 31) == 0) { red[w] = s1; red[8 + w] = s2; }
    __syncthreads();
    float S1 = 0.f, S2 = 0.f;
#pragma unroll
    for (int i = 0; i < 8; i++) { S1 += red[i]; S2 += red[8 + i]; }
    float mean = S1 * (1.f / 256.f);
    float var  = S2 * (1.f / 256.f) - mean * mean;
    h[row * Hdim + j] = (v - mean) * rsqrtf(var + 1e-5f) * gamma[j] + beta[j];
}

__global__ void latent_kernel(const float* __restrict__ h,
                              float* __restrict__ lat)
{
    int b = blockIdx.x, j = threadIdx.x;
    float a = 0.f;
#pragma unroll
    for (int s = 0; s < GL; s++) a += h[(b * GL + s) * Hdim + j];
    lat[b * Hdim + j] = a * (1.f / 16.f);
}

// =====================================================================
// Fusion precompute: Wf = Wih @ Wo (4 k-partials per output)
// =====================================================================
__global__ void fuse_kernel(const float* __restrict__ Wih,
                            const float* __restrict__ Wo,
                            float* __restrict__ Wf)
{
    __shared__ float sw[4 * 256];
    int j  = threadIdx.x;
    int r0 = blockIdx.x * 4;
    for (int i = j; i < 1024; i += 256) sw[i] = Wih[(size_t)r0 * 256 + i];
    __syncthreads();
    float acc[4][4];
#pragma unroll
    for (int rr = 0; rr < 4; rr++)
#pragma unroll
        for (int pp = 0; pp < 4; pp++) acc[rr][pp] = 0.f;
#pragma unroll
    for (int pp = 0; pp < 4; pp++) {
#pragma unroll 4
        for (int kk = 0; kk < 64; kk++) {
            int k = pp * 64 + kk;
            float w = Wo[k * 256 + j];
#pragma unroll
            for (int rr = 0; rr < 4; rr++)
                acc[rr][pp] = fmaf(sw[rr * 256 + k], w, acc[rr][pp]);
        }
    }
#pragma unroll
    for (int rr = 0; rr < 4; rr++)
        Wf[(size_t)(r0 + rr) * 256 + j] =
            (acc[rr][0] + acc[rr][1]) + (acc[rr][2] + acc[rr][3]);
}

__global__ void gia_kernel(const float* __restrict__ Wih,
                           const float* __restrict__ bih,
                           const float* __restrict__ latent,
                           const float* __restrict__ ob,
                           float* __restrict__ gia)
{
    int row  = blockIdx.x;
    int lane = threadIdx.x;
    float w[8];
#pragma unroll
    for (int i = 0; i < 8; i++) w[i] = Wih[(size_t)row * 256 + lane * 8 + i];
    float bi = bih[row];
    for (int v = 0; v < 17; v++) {
        const float* x = (v < 16) ? (latent + v * 256) : ob;
        float a = 0.f;
#pragma unroll
        for (int i = 0; i < 8; i++) a = fmaf(w[i], x[lane * 8 + i], a);
#pragma unroll
        for (int m = 16; m > 0; m >>= 1) a += __shfl_xor_sync(0xffffffffu, a, m);
        if (lane == 0) gia[v * 768 + row] = a + bi;
    }
}

// =====================================================================
// GRU scan: 16 clusters x 8 CTAs; paired st.async.b64 broadcast,
// 8 aggregated arrivals per barrier phase (136 barrier updates/step).
// =====================================================================

#define GRU_CLUSTER 8
__device__ __forceinline__ int SPAD(int i) { return i + ((i >> 5) << 2); }

__device__ __forceinline__ uint32_t smem_u32(const void* p)
{
    return (uint32_t)__cvta_generic_to_shared(p);
}
__device__ __forceinline__ uint32_t mapa_u32(uint32_t a, int rank)
{
    uint32_t ra;
    asm volatile("mapa.shared::cluster.u32 %0, %1, %2;" : "=r"(ra) : "r"(a), "r"(rank));
    return ra;
}
__device__ __forceinline__ void cluster_sync_()
{
    asm volatile("barrier.cluster.arrive.aligned;" ::: "memory");
    asm volatile("barrier.cluster.wait.aligned;"   ::: "memory");
}
__device__ __forceinline__ void mbar_init(uint32_t mbar, uint32_t cnt)
{
    asm volatile("mbarrier.init.shared.b64 [%0], %1;" :: "r"(mbar), "r"(cnt) : "memory");
}
__device__ __forceinline__ void mbar_expect_tx(uint32_t mbar, uint32_t bytes)
{
    asm volatile("mbarrier.arrive.expect_tx.shared.b64 _, [%0], %1;"
                 :: "r"(mbar), "r"(bytes) : "memory");
}
__device__ __forceinline__ void mbar_wait(uint32_t mbar, uint32_t phase)
{
    asm volatile(
        "{\n\t"
        ".reg .pred P;\n\t"
        "WL_%=:\n\t"
        "mbarrier.try_wait.parity.acquire.cta.shared::cta.b64 P, [%0], %1, 0x989680;\n\t"
        "@!P bra WL_%=;\n\t"
        "}" :: "r"(mbar), "r"(phase) : "memory");
}
// 8-byte async store to remote CTA SMEM, tx-completing the remote mbarrier
__device__ __forceinline__ void st_async_b64(uint32_t rdst, unsigned long long v, uint32_t rmbar)
{
    asm volatile(
        "st.async.weak.shared::cluster.mbarrier::complete_tx::bytes.b64 [%0], %1, [%2];"
        :: "r"(rdst), "l"(v), "r"(rmbar) : "memory");
}

__device__ __forceinline__ unsigned long long pack2(float lo, float hi)
{
    unsigned long long u;
    asm("mov.b64 %0, {%1,%2};" : "=l"(u) : "f"(lo), "f"(hi));
    return u;
}
__device__ __forceinline__ float upadd(unsigned long long a)
{
    float lo, hi;
    asm("mov.b64 {%0,%1}, %2;" : "=f"(lo), "=f"(hi) : "l"(a));
    return lo + hi;
}
#define FMA2(acc, x, w) \
    asm("fma.rn.f32x2 %0, %1, %2, %0;" : "+l"(acc) : "l"(x), "l"(w))

__device__ __forceinline__ float sigf(float x)
{
    return __fdividef(1.f, 1.f + __expf(-x));
}
__device__ __forceinline__ float tanhfast(float x)
{
    float e = __expf(-2.f * fabsf(x));
    float t = __fdividef(1.f - e, 1.f + e);
    return copysignf(t, x);
}

__global__ void __cluster_dims__(GRU_CLUSTER, 1, 1) __launch_bounds__(256, 1)
gru_kernel(const float* __restrict__ Wf,  const float* __restrict__ Whh,
           const float* __restrict__ bhh, const float* __restrict__ gia,
           const float* __restrict__ Wo,  const float* __restrict__ ob,
           float* __restrict__ out)
{
    __shared__ __align__(16) float sh[2][296];     // h buffers (rank slice at r*36)
    __shared__ __align__(8)  unsigned long long mb[2];

    unsigned r;
    asm("mov.u32 %0, %%cluster_ctarank;" : "=r"(r));
    int b  = blockIdx.x >> 3;
    int t  = threadIdx.x;
    int G  = t >> 3;
    int s  = t & 7;
    int j  = (int)r * 32 + G;
    int k0 = s * 32;
    bool sender = ((t & 8) == 0);      // even-G threads send packed pairs

    uint32_t mb_l0 = smem_u32(&mb[0]);
    uint32_t mb_l1 = smem_u32(&mb[1]);
    // sender thread delivers (h[j], h[j+1]) to rank s
    uint32_t rmb0  = mapa_u32(mb_l0, s);
    uint32_t rmb1  = mapa_u32(mb_l1, s);
    uint32_t rdst0 = mapa_u32(smem_u32(&sh[0][SPAD(j)]), s);
    uint32_t rdst1 = mapa_u32(smem_u32(&sh[1][SPAD(j)]), s);

    // ---- packed register-resident weights: 5 x 16 u64 = 160 f32 ----
    unsigned long long wr[16], wz[16], wni[16], wnh[16], wo2[16];
#pragma unroll
    for (int i = 0; i < 16; i++) {
        int k = k0 + 2 * i;
        size_t rR = (size_t)j * 256 + k;
        size_t rZ = (size_t)(j + 256) * 256 + k;
        size_t rN = (size_t)(j + 512) * 256 + k;
        wr[i]  = pack2(Wf[rR] + Whh[rR], Wf[rR + 1] + Whh[rR + 1]);
        wz[i]  = pack2(Wf[rZ] + Whh[rZ], Wf[rZ + 1] + Whh[rZ + 1]);
        wni[i] = pack2(Wf[rN],           Wf[rN + 1]);
        wnh[i] = pack2(Whh[rN],          Whh[rN + 1]);
        wo2[i] = pack2(Wo[rR],           Wo[rR + 1]);
    }
    float br  = gia[16 * 768 + j]       + bhh[j];
    float bz  = gia[16 * 768 + 256 + j] + bhh[256 + j];
    float bni = gia[16 * 768 + 512 + j];
    float bnh = bhh[512 + j];
    float bO  = ob[j];

    // ---- mbarrier init (8 arrivals/phase: one per warp), arm both phases ----
    if (t == 0) {
        mbar_init(mb_l0, 8);
        mbar_init(mb_l1, 8);
    }
    __syncthreads();
    if ((t & 31) == 0) {               // warp lane 0: arrive + expect 128 B
        mbar_expect_tx(mb_l0, 128);
        mbar_expect_tx(mb_l1, 128);
    }
    cluster_sync_();                   // all barriers armed cluster-wide

    // ---- peel step 0: x = latent, h_{-1} = 0 ----
    float r0g = sigf(gia[b * 768 + j] + bhh[j]);
    float z0g = sigf(gia[b * 768 + 256 + j] + bhh[256 + j]);
    float hprev = (1.f - z0g) * tanhfast(gia[b * 768 + 512 + j] + r0g * bhh[512 + j]);
    {
        float hp = __shfl_xor_sync(0xffffffffu, hprev, 8);
        if (sender) st_async_b64(rdst0, pack2(hprev, hp), rmb0);
    }

    float* outb = out + (size_t)b * TOTAL;
    int p = 0;
    int ph0 = 0, ph1 = 0;

    for (int n = 1; n < NCH; n++) {
        // wait for h_{n-1} in sh[p]; warp-lane0 re-arms (additive, causal-safe)
        if (p == 0) { mbar_wait(mb_l0, ph0); ph0 ^= 1; if ((t & 31) == 0) mbar_expect_tx(mb_l0, 128); }
        else        { mbar_wait(mb_l1, ph1); ph1 ^= 1; if ((t & 31) == 0) mbar_expect_tx(mb_l1, 128); }

        const float* cur = sh[p];
        unsigned long long ar = 0ull, az = 0ull, ani = 0ull, anh = 0ull, ao = 0ull;
#pragma unroll
        for (int i4 = 0; i4 < 8; i4++) {
            ulonglong2 uv = *reinterpret_cast<const ulonglong2*>(cur + s * 36 + i4 * 4);
            FMA2(ar,  uv.x, wr[2 * i4]);     FMA2(ar,  uv.y, wr[2 * i4 + 1]);
            FMA2(az,  uv.x, wz[2 * i4]);     FMA2(az,  uv.y, wz[2 * i4 + 1]);
            FMA2(ani, uv.x, wni[2 * i4]);    FMA2(ani, uv.y, wni[2 * i4 + 1]);
            FMA2(anh, uv.x, wnh[2 * i4]);    FMA2(anh, uv.y, wnh[2 * i4 + 1]);
            FMA2(ao,  uv.x, wo2[2 * i4]);    FMA2(ao,  uv.y, wo2[2 * i4 + 1]);
        }
        // ---- gate reductions first: h broadcast is the critical path ----
        float vr  = upadd(ar);
        float vz  = upadd(az);
        float vni = upadd(ani);
        float vnh = upadd(anh);
#pragma unroll
        for (int m = 4; m >= 1; m >>= 1) {
            vr  += __shfl_xor_sync(0xffffffffu, vr,  m);
            vz  += __shfl_xor_sync(0xffffffffu, vz,  m);
            vni += __shfl_xor_sync(0xffffffffu, vni, m);
            vnh += __shfl_xor_sync(0xffffffffu, vnh, m);
        }
        float rg   = sigf(vr + br);
        float zg   = sigf(vz + bz);
        float ng   = tanhfast(vni + bni + rg * (vnh + bnh));
        float hnew = fmaf(zg, hprev - ng, ng);
        hprev = hnew;

        int q = p ^ 1;
        float hp = __shfl_xor_sync(0xffffffffu, hnew, 8);
        if (sender) {
            unsigned long long pk = pack2(hnew, hp);
            if (q == 0) st_async_b64(rdst0, pk, rmb0);
            else        st_async_b64(rdst1, pk, rmb1);
        }

        // ---- deferred output-chunk reduction (hidden under DSMEM delivery) ----
        float vo = upadd(ao);
#pragma unroll
        for (int m = 4; m >= 1; m >>= 1)
            vo += __shfl_xor_sync(0xffffffffu, vo, m);
        if (s == 0) outb[(size_t)(n - 1) * 256 + j] = vo + bO;   // chunk_{n-1}
        p = q;
    }

    // ---- epilogue: chunk_1027 = Wo · h_1027 (h_1027 in sh[p]) ----
    if (p == 0) { mbar_wait(mb_l0, ph0); }
    else        { mbar_wait(mb_l1, ph1); }
    {
        const float* cur = sh[p];
        unsigned long long ao = 0ull;
#pragma unroll
        for (int i4 = 0; i4 < 8; i4++) {
            ulonglong2 uv = *reinterpret_cast<const ulonglong2*>(cur + s * 36 + i4 * 4);
            FMA2(ao, uv.x, wo2[2 * i4]);
            FMA2(ao, uv.y, wo2[2 * i4 + 1]);
        }
        float vo = upadd(ao);
#pragma unroll
        for (int m = 4; m >= 1; m >>= 1)
            vo += __shfl_xor_sync(0xffffffffu, vo, m);
        if (s == 0) outb[(size_t)1027 * 256 + j] = vo + bO;
    }
    cluster_sync_();   // keep SMEM alive until all in-flight st.asyncs drain
}

// =====================================================================
// launch
// =====================================================================
extern "C" void kernel_launch(void* const* d_in, const int* in_sizes, int n_in,
                              void* d_out, int out_size)
{
    const float* genome  = (const float*)d_in[0];
    const float* embedW  = (const float*)d_in[1];
    const float* embedB  = (const float*)d_in[2];
    const float* qkvW    = (const float*)d_in[3];
    const float* qkvB    = (const float*)d_in[4];
    const float* projW   = (const float*)d_in[5];
    const float* projB   = (const float*)d_in[6];
    const float* ln1g    = (const float*)d_in[7];
    const float* ln1b    = (const float*)d_in[8];
    const float* ln2g    = (const float*)d_in[9];
    const float* ln2b    = (const float*)d_in[10];
    const float* W1      = (const float*)d_in[11];
    const float* B1      = (const float*)d_in[12];
    const float* W2      = (const float*)d_in[13];
    const float* B2      = (const float*)d_in[14];
    const float* gWih    = (const float*)d_in[15];
    const float* gWhh    = (const float*)d_in[16];
    const float* gbih    = (const float*)d_in[17];
    const float* gbhh    = (const float*)d_in[18];
    const float* oW      = (const float*)d_in[19];
    const float* oB      = (const float*)d_in[20];
    float* out = (float*)d_out;

    float *p_h, *p_qkv, *p_attn, *p_tmp, *p_ffn, *p_lat, *p_wf, *p_gia;
    cudaGetSymbolAddress((void**)&p_h,    g_h);
    cudaGetSymbolAddress((void**)&p_qkv,  g_qkv);
    cudaGetSymbolAddress((void**)&p_attn, g_attn);
    cudaGetSymbolAddress((void**)&p_tmp,  g_tmp);
    cudaGetSymbolAddress((void**)&p_ffn,  g_ffn);
    cudaGetSymbolAddress((void**)&p_lat,  g_latent);
    cudaGetSymbolAddress((void**)&p_wf,   g_wf);
    cudaGetSymbolAddress((void**)&p_gia,  g_gia);

    fuse_kernel<<<192, 256>>>(gWih, oW, p_wf);

    embed_kernel<<<BATCH * GL, Hdim>>>(genome, embedW, embedB, p_h);

    for (int l = 0; l < NLAY; l++) {
        gemm_rows4<3 * Hdim, Hdim, false><<<64, 3 * Hdim>>>(
            p_h, qkvW + (size_t)l * 3 * Hdim * Hdim, qkvB + l * 3 * Hdim, p_qkv);
        attn_kernel<<<BATCH * NH, 256>>>(p_qkv, p_attn);
        gemm_rows4<Hdim, Hdim, false><<<64, Hdim>>>(
            p_attn, projW + (size_t)l * Hdim * Hdim, projB + l * Hdim, p_tmp);
        addln_kernel<<<BATCH * GL, Hdim>>>(p_tmp, p_h, ln1g + l * Hdim, ln1b + l * Hdim);
        gemm_rows4<4 * Hdim, Hdim, true><<<64, 4 * Hdim>>>(
            p_h, W1 + (size_t)l * 4 * Hdim * Hdim, B1 + l * 4 * Hdim, p_ffn);
        gemm_rows4<Hdim, 4 * Hdim, false><<<64, Hdim>>>(
            p_ffn, W2 + (size_t)l * 4 * Hdim * Hdim, B2 + l * Hdim, p_tmp);
        addln_kernel<<<BATCH * GL, Hdim>>>(p_tmp, p_h, ln2g + l * Hdim, ln2b + l * Hdim);
    }

    latent_kernel<<<BATCH, Hdim>>>(p_h, p_lat);
    gia_kernel<<<768, 32>>>(gWih, gbih, p_lat, oB, p_gia);

    gru_kernel<<<BATCH * GRU_CLUSTER, 256>>>(p_wf, gWhh, gbhh, p_gia, oW, oB, out);
}

// round 10
// speedup vs baseline: 1.1220x; 1.1220x over previous
#include <cuda_runtime.h>
#include <cstdint>
#include <cstdio>

// ---------------- problem constants ----------------
#define Hdim   256
#define GD     16
#define GL     16
#define NLAY   2
#define NH     4
#define DH     64
#define CS     256
#define TOTAL  263168
#define NCH    1028
#define BATCH  16

// ---------------- device scratch (no allocation allowed) ----------------
__device__ float g_h[BATCH * GL * Hdim];
__device__ float g_qkv[BATCH * GL * 3 * Hdim];
__device__ float g_attn[BATCH * GL * Hdim];
__device__ float g_tmp[BATCH * GL * Hdim];
__device__ float g_ffn[BATCH * GL * 4 * Hdim];
__device__ float g_latent[BATCH * Hdim];
__device__ float g_wf[768 * 256];      // fused Wih @ Wo
__device__ float g_gia[17 * 768];      // rows 0..15: gi0 per batch; row 16: Wih·ob + bih

// =====================================================================
// Transformer preamble — dot products split into 4 partials (chain/4)
// =====================================================================

__global__ void embed_kernel(const float* __restrict__ g,
                             const float* __restrict__ W,
                             const float* __restrict__ bias,
                             float* __restrict__ h)
{
    int row = blockIdx.x;
    int j   = threadIdx.x;
    __shared__ float sg[GD];
    if (j < GD) sg[j] = g[row * GD + j];
    __syncthreads();
    float a = bias[j];
    const float* w = W + j * GD;
#pragma unroll
    for (int d = 0; d < GD; d++) a = fmaf(sg[d], w[d], a);
    h[row * Hdim + j] = a;
}

template<int NOUT, int KD, bool RELU>
__global__ void gemm_rows4(const float* __restrict__ X,
                           const float* __restrict__ W,
                           const float* __restrict__ bias,
                           float* __restrict__ Y)
{
    __shared__ float sx[4 * KD];
    int j  = threadIdx.x;
    int r0 = blockIdx.x * 4;
    for (int i = j; i < 4 * KD; i += NOUT) sx[i] = X[r0 * KD + i];
    __syncthreads();
    const float* w = W + (size_t)j * KD;
    float acc[4][4];
#pragma unroll
    for (int rr = 0; rr < 4; rr++)
#pragma unroll
        for (int pp = 0; pp < 4; pp++) acc[rr][pp] = 0.f;
    constexpr int KQ = KD / 4;
#pragma unroll
    for (int pp = 0; pp < 4; pp++) {
        const float* wp = w + pp * KQ;
#pragma unroll 4
        for (int k = 0; k < KQ; k += 4) {
            float4 wv = *reinterpret_cast<const float4*>(wp + k);
#pragma unroll
            for (int rr = 0; rr < 4; rr++) {
                const float* sxr = sx + rr * KD + pp * KQ + k;
                acc[rr][pp] = fmaf(sxr[0], wv.x, acc[rr][pp]);
                acc[rr][pp] = fmaf(sxr[1], wv.y, acc[rr][pp]);
                acc[rr][pp] = fmaf(sxr[2], wv.z, acc[rr][pp]);
                acc[rr][pp] = fmaf(sxr[3], wv.w, acc[rr][pp]);
            }
        }
    }
    float bv = bias[j];
#pragma unroll
    for (int rr = 0; rr < 4; rr++) {
        float a = bv + ((acc[rr][0] + acc[rr][1]) + (acc[rr][2] + acc[rr][3]));
        if (RELU) a = fmaxf(a, 0.f);
        Y[(size_t)(r0 + rr) * NOUT + j] = a;
    }
}

__global__ void attn_kernel(const float* __restrict__ qkv,
                            float* __restrict__ obuf)
{
    int b    = blockIdx.x >> 2;
    int head = blockIdx.x & 3;
    __shared__ float sq[GL][DH], sk[GL][DH], sv[GL][DH], sa[GL][GL];
    int tid = threadIdx.x;
    for (int i = tid; i < GL * DH; i += 256) {
        int s_ = i >> 6, d = i & 63;
        int base = (b * GL + s_) * (3 * Hdim) + head * DH + d;
        sq[s_][d] = qkv[base];
        sk[s_][d] = qkv[base + Hdim];
        sv[s_][d] = qkv[base + 2 * Hdim];
    }
    __syncthreads();
    int s_ = tid >> 4, t_ = tid & 15;
    float p0 = 0.f, p1 = 0.f;
#pragma unroll
    for (int d = 0; d < DH; d += 2) {
        p0 = fmaf(sq[s_][d],     sk[t_][d],     p0);
        p1 = fmaf(sq[s_][d + 1], sk[t_][d + 1], p1);
    }
    float sc = (p0 + p1) * 0.125f;
    float mx = sc;
#pragma unroll
    for (int m = 8; m > 0; m >>= 1) mx = fmaxf(mx, __shfl_xor_sync(0xffffffffu, mx, m));
    float e = __expf(sc - mx);
    float sum = e;
#pragma unroll
    for (int m = 8; m > 0; m >>= 1) sum += __shfl_xor_sync(0xffffffffu, sum, m);
    sa[s_][t_] = e / sum;
    __syncthreads();
    int d4 = tid & 15; s_ = tid >> 4;
#pragma unroll
    for (int dd = 0; dd < 4; dd++) {
        int d = d4 * 4 + dd;
        float acc = 0.f;
#pragma unroll
        for (int t = 0; t < GL; t++) acc = fmaf(sa[s_][t], sv[t][d], acc);
        obuf[(b * GL + s_) * Hdim + head * DH + d] = acc;
    }
}

__global__ void addln_kernel(const float* __restrict__ y,
                             float* __restrict__ h,
                             const float* __restrict__ gamma,
                             const float* __restrict__ beta)
{
    int row = blockIdx.x;
    int j   = threadIdx.x;
    __shared__ float red[16];
    float v = y[row * Hdim + j] + h[row * Hdim + j];
    float s1 = v, s2 = v * v;
#pragma unroll
    for (int m = 16; m > 0; m >>= 1) {
        s1 += __shfl_xor_sync(0xffffffffu, s1, m);
        s2 += __shfl_xor_sync(0xffffffffu, s2, m);
    }
    int w = j >> 5;
    if ((j & 31) == 0) { red[w] = s1; red[8 + w] = s2; }
    __syncthreads();
    float S1 = 0.f, S2 = 0.f;
#pragma unroll
    for (int i = 0; i < 8; i++) { S1 += red[i]; S2 += red[8 + i]; }
    float mean = S1 * (1.f / 256.f);
    float var  = S2 * (1.f / 256.f) - mean * mean;
    h[row * Hdim + j] = (v - mean) * rsqrtf(var + 1e-5f) * gamma[j] + beta[j];
}

__global__ void latent_kernel(const float* __restrict__ h,
                              float* __restrict__ lat)
{
    int b = blockIdx.x, j = threadIdx.x;
    float a = 0.f;
#pragma unroll
    for (int s = 0; s < GL; s++) a += h[(b * GL + s) * Hdim + j];
    lat[b * Hdim + j] = a * (1.f / 16.f);
}

// =====================================================================
// Fusion precompute: Wf = Wih @ Wo (4 k-partials per output)
// =====================================================================
__global__ void fuse_kernel(const float* __restrict__ Wih,
                            const float* __restrict__ Wo,
                            float* __restrict__ Wf)
{
    __shared__ float sw[4 * 256];
    int j  = threadIdx.x;
    int r0 = blockIdx.x * 4;
    for (int i = j; i < 1024; i += 256) sw[i] = Wih[(size_t)r0 * 256 + i];
    __syncthreads();
    float acc[4][4];
#pragma unroll
    for (int rr = 0; rr < 4; rr++)
#pragma unroll
        for (int pp = 0; pp < 4; pp++) acc[rr][pp] = 0.f;
#pragma unroll
    for (int pp = 0; pp < 4; pp++) {
#pragma unroll 4
        for (int kk = 0; kk < 64; kk++) {
            int k = pp * 64 + kk;
            float w = Wo[k * 256 + j];
#pragma unroll
            for (int rr = 0; rr < 4; rr++)
                acc[rr][pp] = fmaf(sw[rr * 256 + k], w, acc[rr][pp]);
        }
    }
#pragma unroll
    for (int rr = 0; rr < 4; rr++)
        Wf[(size_t)(r0 + rr) * 256 + j] =
            (acc[rr][0] + acc[rr][1]) + (acc[rr][2] + acc[rr][3]);
}

__global__ void gia_kernel(const float* __restrict__ Wih,
                           const float* __restrict__ bih,
                           const float* __restrict__ latent,
                           const float* __restrict__ ob,
                           float* __restrict__ gia)
{
    int row  = blockIdx.x;
    int lane = threadIdx.x;
    float w[8];
#pragma unroll
    for (int i = 0; i < 8; i++) w[i] = Wih[(size_t)row * 256 + lane * 8 + i];
    float bi = bih[row];
    for (int v = 0; v < 17; v++) {
        const float* x = (v < 16) ? (latent + v * 256) : ob;
        float a = 0.f;
#pragma unroll
        for (int i = 0; i < 8; i++) a = fmaf(w[i], x[lane * 8 + i], a);
#pragma unroll
        for (int m = 16; m > 0; m >>= 1) a += __shfl_xor_sync(0xffffffffu, a, m);
        if (lane == 0) gia[v * 768 + row] = a + bi;
    }
}

// =====================================================================
// GRU scan: 16 clusters x 8 CTAs; per-thread st.async broadcast (R7 scheme),
// tanh.approx activations to shorten the serial chain.
// =====================================================================

#define GRU_CLUSTER 8
__device__ __forceinline__ int SPAD(int i) { return i + ((i >> 5) << 2); }

__device__ __forceinline__ uint32_t smem_u32(const void* p)
{
    return (uint32_t)__cvta_generic_to_shared(p);
}
__device__ __forceinline__ uint32_t mapa_u32(uint32_t a, int rank)
{
    uint32_t ra;
    asm volatile("mapa.shared::cluster.u32 %0, %1, %2;" : "=r"(ra) : "r"(a), "r"(rank));
    return ra;
}
__device__ __forceinline__ void cluster_sync_()
{
    asm volatile("barrier.cluster.arrive.aligned;" ::: "memory");
    asm volatile("barrier.cluster.wait.aligned;"   ::: "memory");
}
__device__ __forceinline__ void mbar_init(uint32_t mbar, uint32_t cnt)
{
    asm volatile("mbarrier.init.shared.b64 [%0], %1;" :: "r"(mbar), "r"(cnt) : "memory");
}
__device__ __forceinline__ void mbar_expect_tx(uint32_t mbar, uint32_t bytes)
{
    asm volatile("mbarrier.arrive.expect_tx.shared.b64 _, [%0], %1;"
                 :: "r"(mbar), "r"(bytes) : "memory");
}
__device__ __forceinline__ void mbar_wait(uint32_t mbar, uint32_t phase)
{
    asm volatile(
        "{\n\t"
        ".reg .pred P;\n\t"
        "WL_%=:\n\t"
        "mbarrier.try_wait.parity.acquire.cta.shared::cta.b64 P, [%0], %1, 0x989680;\n\t"
        "@!P bra WL_%=;\n\t"
        "}" :: "r"(mbar), "r"(phase) : "memory");
}
// single-f32 async store to remote CTA SMEM, tx-completing the remote mbarrier
__device__ __forceinline__ void st_async_f32(uint32_t rdst, float v, uint32_t rmbar)
{
    asm volatile(
        "st.async.weak.shared::cluster.mbarrier::complete_tx::bytes.b32 [%0], %1, [%2];"
        :: "r"(rdst), "r"(__float_as_uint(v)), "r"(rmbar) : "memory");
}

__device__ __forceinline__ unsigned long long pack2(float lo, float hi)
{
    unsigned long long u;
    asm("mov.b64 %0, {%1,%2};" : "=l"(u) : "f"(lo), "f"(hi));
    return u;
}
__device__ __forceinline__ float upadd(unsigned long long a)
{
    float lo, hi;
    asm("mov.b64 {%0,%1}, %2;" : "=f"(lo), "=f"(hi) : "l"(a));
    return lo + hi;
}
#define FMA2(acc, x, w) \
    asm("fma.rn.f32x2 %0, %1, %2, %0;" : "+l"(acc) : "l"(x), "l"(w))

__device__ __forceinline__ float tanha(float x)
{
    float y;
    asm("tanh.approx.f32 %0, %1;" : "=f"(y) : "f"(x));
    return y;
}
__device__ __forceinline__ float sigt(float x)    // sigmoid via tanh.approx
{
    return fmaf(0.5f, tanha(0.5f * x), 0.5f);
}

__global__ void __cluster_dims__(GRU_CLUSTER, 1, 1) __launch_bounds__(256, 1)
gru_kernel(const float* __restrict__ Wf,  const float* __restrict__ Whh,
           const float* __restrict__ bhh, const float* __restrict__ gia,
           const float* __restrict__ Wo,  const float* __restrict__ ob,
           float* __restrict__ out)
{
    __shared__ __align__(16) float sh[2][296];     // h buffers (rank slice at r*36)
    __shared__ __align__(8)  unsigned long long mb[2];

    unsigned r;
    asm("mov.u32 %0, %%cluster_ctarank;" : "=r"(r));
    int b  = blockIdx.x >> 3;
    int t  = threadIdx.x;
    int G  = t >> 3;
    int s  = t & 7;
    int j  = (int)r * 32 + G;
    int k0 = s * 32;

    uint32_t mb_l0 = smem_u32(&mb[0]);
    uint32_t mb_l1 = smem_u32(&mb[1]);
    // per-thread remote targets: this thread delivers h[j] to rank s
    uint32_t rmb0  = mapa_u32(mb_l0, s);
    uint32_t rmb1  = mapa_u32(mb_l1, s);
    uint32_t rdst0 = mapa_u32(smem_u32(&sh[0][SPAD(j)]), s);
    uint32_t rdst1 = mapa_u32(smem_u32(&sh[1][SPAD(j)]), s);

    // ---- packed register-resident weights: 5 x 16 u64 = 160 f32 ----
    unsigned long long wr[16], wz[16], wni[16], wnh[16], wo2[16];
#pragma unroll
    for (int i = 0; i < 16; i++) {
        int k = k0 + 2 * i;
        size_t rR = (size_t)j * 256 + k;
        size_t rZ = (size_t)(j + 256) * 256 + k;
        size_t rN = (size_t)(j + 512) * 256 + k;
        wr[i]  = pack2(Wf[rR] + Whh[rR], Wf[rR + 1] + Whh[rR + 1]);
        wz[i]  = pack2(Wf[rZ] + Whh[rZ], Wf[rZ + 1] + Whh[rZ + 1]);
        wni[i] = pack2(Wf[rN],           Wf[rN + 1]);
        wnh[i] = pack2(Whh[rN],          Whh[rN + 1]);
        wo2[i] = pack2(Wo[rR],           Wo[rR + 1]);
    }
    float br  = gia[16 * 768 + j]       + bhh[j];
    float bz  = gia[16 * 768 + 256 + j] + bhh[256 + j];
    float bni = gia[16 * 768 + 512 + j];
    float bnh = bhh[512 + j];
    float bO  = ob[j];

    // ---- mbarrier init (count = 256 arrives/phase), arm both phases ----
    if (t == 0) {
        mbar_init(mb_l0, 256);
        mbar_init(mb_l1, 256);
    }
    __syncthreads();
    mbar_expect_tx(mb_l0, 4);   // every thread: arrive + expect its 4 incoming bytes
    mbar_expect_tx(mb_l1, 4);
    cluster_sync_();            // all barriers armed cluster-wide before any st.async

    // ---- peel step 0: x = latent, h_{-1} = 0 ----
    float r0g = sigt(gia[b * 768 + j] + bhh[j]);
    float z0g = sigt(gia[b * 768 + 256 + j] + bhh[256 + j]);
    float hprev = (1.f - z0g) * tanha(gia[b * 768 + 512 + j] + r0g * bhh[512 + j]);
    st_async_f32(rdst0, hprev, rmb0);     // lane s -> rank s, buffer 0

    float* outb = out + (size_t)b * TOTAL;
    int p = 0;
    int ph0 = 0, ph1 = 0;

    for (int n = 1; n < NCH; n++) {
        // wait for h_{n-1} in sh[p]; immediately re-arm this barrier (additive)
        if (p == 0) { mbar_wait(mb_l0, ph0); ph0 ^= 1; mbar_expect_tx(mb_l0, 4); }
        else        { mbar_wait(mb_l1, ph1); ph1 ^= 1; mbar_expect_tx(mb_l1, 4); }

        const float* cur = sh[p];
        unsigned long long ar = 0ull, az = 0ull, ani = 0ull, anh = 0ull, ao = 0ull;
#pragma unroll
        for (int i4 = 0; i4 < 8; i4++) {
            ulonglong2 uv = *reinterpret_cast<const ulonglong2*>(cur + s * 36 + i4 * 4);
            FMA2(ar,  uv.x, wr[2 * i4]);     FMA2(ar,  uv.y, wr[2 * i4 + 1]);
            FMA2(az,  uv.x, wz[2 * i4]);     FMA2(az,  uv.y, wz[2 * i4 + 1]);
            FMA2(ani, uv.x, wni[2 * i4]);    FMA2(ani, uv.y, wni[2 * i4 + 1]);
            FMA2(anh, uv.x, wnh[2 * i4]);    FMA2(anh, uv.y, wnh[2 * i4 + 1]);
            FMA2(ao,  uv.x, wo2[2 * i4]);    FMA2(ao,  uv.y, wo2[2 * i4 + 1]);
        }
        // ---- gate reductions first: h broadcast is the critical path ----
        float vr  = upadd(ar);
        float vz  = upadd(az);
        float vni = upadd(ani);
        float vnh = upadd(anh);
#pragma unroll
        for (int m = 4; m >= 1; m >>= 1) {
            vr  += __shfl_xor_sync(0xffffffffu, vr,  m);
            vz  += __shfl_xor_sync(0xffffffffu, vz,  m);
            vni += __shfl_xor_sync(0xffffffffu, vni, m);
            vnh += __shfl_xor_sync(0xffffffffu, vnh, m);
        }
        float rg   = sigt(vr + br);
        float zg   = sigt(vz + bz);
        float ng   = tanha(vni + bni + rg * (vnh + bnh));
        float hnew = fmaf(zg, hprev - ng, ng);
        hprev = hnew;

        int q = p ^ 1;
        if (q == 0) st_async_f32(rdst0, hnew, rmb0);   // fire-and-forget broadcast
        else        st_async_f32(rdst1, hnew, rmb1);

        // ---- deferred output-chunk reduction (hidden under DSMEM delivery) ----
        float vo = upadd(ao);
#pragma unroll
        for (int m = 4; m >= 1; m >>= 1)
            vo += __shfl_xor_sync(0xffffffffu, vo, m);
        if (s == 0) outb[(size_t)(n - 1) * 256 + j] = vo + bO;   // chunk_{n-1}
        p = q;
    }

    // ---- epilogue: chunk_1027 = Wo · h_1027 (h_1027 in sh[p]) ----
    if (p == 0) { mbar_wait(mb_l0, ph0); }
    else        { mbar_wait(mb_l1, ph1); }
    {
        const float* cur = sh[p];
        unsigned long long ao = 0ull;
#pragma unroll
        for (int i4 = 0; i4 < 8; i4++) {
            ulonglong2 uv = *reinterpret_cast<const ulonglong2*>(cur + s * 36 + i4 * 4);
            FMA2(ao, uv.x, wo2[2 * i4]);
            FMA2(ao, uv.y, wo2[2 * i4 + 1]);
        }
        float vo = upadd(ao);
#pragma unroll
        for (int m = 4; m >= 1; m >>= 1)
            vo += __shfl_xor_sync(0xffffffffu, vo, m);
        if (s == 0) outb[(size_t)1027 * 256 + j] = vo + bO;
    }
    cluster_sync_();   // keep SMEM alive until all in-flight st.asyncs drain
}

// =====================================================================
// launch
// =====================================================================
extern "C" void kernel_launch(void* const* d_in, const int* in_sizes, int n_in,
                              void* d_out, int out_size)
{
    const float* genome  = (const float*)d_in[0];
    const float* embedW  = (const float*)d_in[1];
    const float* embedB  = (const float*)d_in[2];
    const float* qkvW    = (const float*)d_in[3];
    const float* qkvB    = (const float*)d_in[4];
    const float* projW   = (const float*)d_in[5];
    const float* projB   = (const float*)d_in[6];
    const float* ln1g    = (const float*)d_in[7];
    const float* ln1b    = (const float*)d_in[8];
    const float* ln2g    = (const float*)d_in[9];
    const float* ln2b    = (const float*)d_in[10];
    const float* W1      = (const float*)d_in[11];
    const float* B1      = (const float*)d_in[12];
    const float* W2      = (const float*)d_in[13];
    const float* B2      = (const float*)d_in[14];
    const float* gWih    = (const float*)d_in[15];
    const float* gWhh    = (const float*)d_in[16];
    const float* gbih    = (const float*)d_in[17];
    const float* gbhh    = (const float*)d_in[18];
    const float* oW      = (const float*)d_in[19];
    const float* oB      = (const float*)d_in[20];
    float* out = (float*)d_out;

    float *p_h, *p_qkv, *p_attn, *p_tmp, *p_ffn, *p_lat, *p_wf, *p_gia;
    cudaGetSymbolAddress((void**)&p_h,    g_h);
    cudaGetSymbolAddress((void**)&p_qkv,  g_qkv);
    cudaGetSymbolAddress((void**)&p_attn, g_attn);
    cudaGetSymbolAddress((void**)&p_tmp,  g_tmp);
    cudaGetSymbolAddress((void**)&p_ffn,  g_ffn);
    cudaGetSymbolAddress((void**)&p_lat,  g_latent);
    cudaGetSymbolAddress((void**)&p_wf,   g_wf);
    cudaGetSymbolAddress((void**)&p_gia,  g_gia);

    fuse_kernel<<<192, 256>>>(gWih, oW, p_wf);

    embed_kernel<<<BATCH * GL, Hdim>>>(genome, embedW, embedB, p_h);

    for (int l = 0; l < NLAY; l++) {
        gemm_rows4<3 * Hdim, Hdim, false><<<64, 3 * Hdim>>>(
            p_h, qkvW + (size_t)l * 3 * Hdim * Hdim, qkvB + l * 3 * Hdim, p_qkv);
        attn_kernel<<<BATCH * NH, 256>>>(p_qkv, p_attn);
        gemm_rows4<Hdim, Hdim, false><<<64, Hdim>>>(
            p_attn, projW + (size_t)l * Hdim * Hdim, projB + l * Hdim, p_tmp);
        addln_kernel<<<BATCH * GL, Hdim>>>(p_tmp, p_h, ln1g + l * Hdim, ln1b + l * Hdim);
        gemm_rows4<4 * Hdim, Hdim, true><<<64, 4 * Hdim>>>(
            p_h, W1 + (size_t)l * 4 * Hdim * Hdim, B1 + l * 4 * Hdim, p_ffn);
        gemm_rows4<Hdim, 4 * Hdim, false><<<64, Hdim>>>(
            p_ffn, W2 + (size_t)l * 4 * Hdim * Hdim, B2 + l * Hdim, p_tmp);
        addln_kernel<<<BATCH * GL, Hdim>>>(p_tmp, p_h, ln2g + l * Hdim, ln2b + l * Hdim);
    }

    latent_kernel<<<BATCH, Hdim>>>(p_h, p_lat);
    gia_kernel<<<768, 32>>>(gWih, gbih, p_lat, oB, p_gia);

    gru_kernel<<<BATCH * GRU_CLUSTER, 256>>>(p_wf, gWhh, gbhh, p_gia, oW, oB, out);
}

// round 11
// speedup vs baseline: 1.3364x; 1.1910x over previous
#include <cuda_runtime.h>
#include <cstdint>
#include <cstdio>

// ---------------- problem constants ----------------
#define Hdim   256
#define GD     16
#define GL     16
#define NLAY   2
#define NH     4
#define DH     64
#define CS     256
#define TOTAL  263168
#define NCH    1028
#define BATCH  16

// ---------------- device scratch (no allocation allowed) ----------------
__device__ float g_h[BATCH * GL * Hdim];
__device__ float g_qkv[BATCH * GL * 3 * Hdim];
__device__ float g_attn[BATCH * GL * Hdim];
__device__ float g_tmp[BATCH * GL * Hdim];
__device__ float g_ffn[BATCH * GL * 4 * Hdim];
__device__ float g_latent[BATCH * Hdim];
__device__ float g_wf[768 * 256];      // fused Wih @ Wo
__device__ float g_gia[17 * 768];      // rows 0..15: gi0 per batch; row 16: Wih·ob + bih

// =====================================================================
// Transformer preamble (as R10 winner)
// =====================================================================

__global__ void embed_kernel(const float* __restrict__ g,
                             const float* __restrict__ W,
                             const float* __restrict__ bias,
                             float* __restrict__ h)
{
    int row = blockIdx.x;
    int j   = threadIdx.x;
    __shared__ float sg[GD];
    if (j < GD) sg[j] = g[row * GD + j];
    __syncthreads();
    float a = bias[j];
    const float* w = W + j * GD;
#pragma unroll
    for (int d = 0; d < GD; d++) a = fmaf(sg[d], w[d], a);
    h[row * Hdim + j] = a;
}

template<int NOUT, int KD, bool RELU>
__global__ void gemm_rows4(const float* __restrict__ X,
                           const float* __restrict__ W,
                           const float* __restrict__ bias,
                           float* __restrict__ Y)
{
    __shared__ float sx[4 * KD];
    int j  = threadIdx.x;
    int r0 = blockIdx.x * 4;
    for (int i = j; i < 4 * KD; i += NOUT) sx[i] = X[r0 * KD + i];
    __syncthreads();
    const float* w = W + (size_t)j * KD;
    float acc[4][4];
#pragma unroll
    for (int rr = 0; rr < 4; rr++)
#pragma unroll
        for (int pp = 0; pp < 4; pp++) acc[rr][pp] = 0.f;
    constexpr int KQ = KD / 4;
#pragma unroll
    for (int pp = 0; pp < 4; pp++) {
        const float* wp = w + pp * KQ;
#pragma unroll 4
        for (int k = 0; k < KQ; k += 4) {
            float4 wv = *reinterpret_cast<const float4*>(wp + k);
#pragma unroll
            for (int rr = 0; rr < 4; rr++) {
                const float* sxr = sx + rr * KD + pp * KQ + k;
                acc[rr][pp] = fmaf(sxr[0], wv.x, acc[rr][pp]);
                acc[rr][pp] = fmaf(sxr[1], wv.y, acc[rr][pp]);
                acc[rr][pp] = fmaf(sxr[2], wv.z, acc[rr][pp]);
                acc[rr][pp] = fmaf(sxr[3], wv.w, acc[rr][pp]);
            }
        }
    }
    float bv = bias[j];
#pragma unroll
    for (int rr = 0; rr < 4; rr++) {
        float a = bv + ((acc[rr][0] + acc[rr][1]) + (acc[rr][2] + acc[rr][3]));
        if (RELU) a = fmaxf(a, 0.f);
        Y[(size_t)(r0 + rr) * NOUT + j] = a;
    }
}

__global__ void attn_kernel(const float* __restrict__ qkv,
                            float* __restrict__ obuf)
{
    int b    = blockIdx.x >> 2;
    int head = blockIdx.x & 3;
    __shared__ float sq[GL][DH], sk[GL][DH], sv[GL][DH], sa[GL][GL];
    int tid = threadIdx.x;
    for (int i = tid; i < GL * DH; i += 256) {
        int s_ = i >> 6, d = i & 63;
        int base = (b * GL + s_) * (3 * Hdim) + head * DH + d;
        sq[s_][d] = qkv[base];
        sk[s_][d] = qkv[base + Hdim];
        sv[s_][d] = qkv[base + 2 * Hdim];
    }
    __syncthreads();
    int s_ = tid >> 4, t_ = tid & 15;
    float p0 = 0.f, p1 = 0.f;
#pragma unroll
    for (int d = 0; d < DH; d += 2) {
        p0 = fmaf(sq[s_][d],     sk[t_][d],     p0);
        p1 = fmaf(sq[s_][d + 1], sk[t_][d + 1], p1);
    }
    float sc = (p0 + p1) * 0.125f;
    float mx = sc;
#pragma unroll
    for (int m = 8; m > 0; m >>= 1) mx = fmaxf(mx, __shfl_xor_sync(0xffffffffu, mx, m));
    float e = __expf(sc - mx);
    float sum = e;
#pragma unroll
    for (int m = 8; m > 0; m >>= 1) sum += __shfl_xor_sync(0xffffffffu, sum, m);
    sa[s_][t_] = e / sum;
    __syncthreads();
    int d4 = tid & 15; s_ = tid >> 4;
#pragma unroll
    for (int dd = 0; dd < 4; dd++) {
        int d = d4 * 4 + dd;
        float acc = 0.f;
#pragma unroll
        for (int t = 0; t < GL; t++) acc = fmaf(sa[s_][t], sv[t][d], acc);
        obuf[(b * GL + s_) * Hdim + head * DH + d] = acc;
    }
}

__global__ void addln_kernel(const float* __restrict__ y,
                             float* __restrict__ h,
                             const float* __restrict__ gamma,
                             const float* __restrict__ beta)
{
    int row = blockIdx.x;
    int j   = threadIdx.x;
    __shared__ float red[16];
    float v = y[row * Hdim + j] + h[row * Hdim + j];
    float s1 = v, s2 = v * v;
#pragma unroll
    for (int m = 16; m > 0; m >>= 1) {
        s1 += __shfl_xor_sync(0xffffffffu, s1, m);
        s2 += __shfl_xor_sync(0xffffffffu, s2, m);
    }
    int w = j >> 5;
    if ((j & 31) == 0) { red[w] = s1; red[8 + w] = s2; }
    __syncthreads();
    float S1 = 0.f, S2 = 0.f;
#pragma unroll
    for (int i = 0; i < 8; i++) { S1 += red[i]; S2 += red[8 + i]; }
    float mean = S1 * (1.f / 256.f);
    float var  = S2 * (1.f / 256.f) - mean * mean;
    h[row * Hdim + j] = (v - mean) * rsqrtf(var + 1e-5f) * gamma[j] + beta[j];
}

__global__ void latent_kernel(const float* __restrict__ h,
                              float* __restrict__ lat)
{
    int b = blockIdx.x, j = threadIdx.x;
    float a = 0.f;
#pragma unroll
    for (int s = 0; s < GL; s++) a += h[(b * GL + s) * Hdim + j];
    lat[b * Hdim + j] = a * (1.f / 16.f);
}

// =====================================================================
// Fusion precompute: Wf = Wih @ Wo (4 k-partials per output)
// =====================================================================
__global__ void fuse_kernel(const float* __restrict__ Wih,
                            const float* __restrict__ Wo,
                            float* __restrict__ Wf)
{
    __shared__ float sw[4 * 256];
    int j  = threadIdx.x;
    int r0 = blockIdx.x * 4;
    for (int i = j; i < 1024; i += 256) sw[i] = Wih[(size_t)r0 * 256 + i];
    __syncthreads();
    float acc[4][4];
#pragma unroll
    for (int rr = 0; rr < 4; rr++)
#pragma unroll
        for (int pp = 0; pp < 4; pp++) acc[rr][pp] = 0.f;
#pragma unroll
    for (int pp = 0; pp < 4; pp++) {
#pragma unroll 4
        for (int kk = 0; kk < 64; kk++) {
            int k = pp * 64 + kk;
            float w = Wo[k * 256 + j];
#pragma unroll
            for (int rr = 0; rr < 4; rr++)
                acc[rr][pp] = fmaf(sw[rr * 256 + k], w, acc[rr][pp]);
        }
    }
#pragma unroll
    for (int rr = 0; rr < 4; rr++)
        Wf[(size_t)(r0 + rr) * 256 + j] =
            (acc[rr][0] + acc[rr][1]) + (acc[rr][2] + acc[rr][3]);
}

__global__ void gia_kernel(const float* __restrict__ Wih,
                           const float* __restrict__ bih,
                           const float* __restrict__ latent,
                           const float* __restrict__ ob,
                           float* __restrict__ gia)
{
    int row  = blockIdx.x;
    int lane = threadIdx.x;
    float w[8];
#pragma unroll
    for (int i = 0; i < 8; i++) w[i] = Wih[(size_t)row * 256 + lane * 8 + i];
    float bi = bih[row];
    for (int v = 0; v < 17; v++) {
        const float* x = (v < 16) ? (latent + v * 256) : ob;
        float a = 0.f;
#pragma unroll
        for (int i = 0; i < 8; i++) a = fmaf(w[i], x[lane * 8 + i], a);
#pragma unroll
        for (int m = 16; m > 0; m >>= 1) a += __shfl_xor_sync(0xffffffffu, a, m);
        if (lane == 0) gia[v * 768 + row] = a + bi;
    }
}

// =====================================================================
// GRU scan: 8 clusters x 8 CTAs, TWO batches per cluster interleaved.
// Shared register-resident weights; per-thread st.async broadcast;
// each batch's comm latency hides under the other batch's compute.
// =====================================================================

#define GRU_CLUSTER 8
__device__ __forceinline__ int SPAD(int i) { return i + ((i >> 5) << 2); }

__device__ __forceinline__ uint32_t smem_u32(const void* p)
{
    return (uint32_t)__cvta_generic_to_shared(p);
}
__device__ __forceinline__ uint32_t mapa_u32(uint32_t a, int rank)
{
    uint32_t ra;
    asm volatile("mapa.shared::cluster.u32 %0, %1, %2;" : "=r"(ra) : "r"(a), "r"(rank));
    return ra;
}
__device__ __forceinline__ void cluster_sync_()
{
    asm volatile("barrier.cluster.arrive.aligned;" ::: "memory");
    asm volatile("barrier.cluster.wait.aligned;"   ::: "memory");
}
__device__ __forceinline__ void mbar_init(uint32_t mbar, uint32_t cnt)
{
    asm volatile("mbarrier.init.shared.b64 [%0], %1;" :: "r"(mbar), "r"(cnt) : "memory");
}
__device__ __forceinline__ void mbar_expect_tx(uint32_t mbar, uint32_t bytes)
{
    asm volatile("mbarrier.arrive.expect_tx.shared.b64 _, [%0], %1;"
                 :: "r"(mbar), "r"(bytes) : "memory");
}
__device__ __forceinline__ void mbar_wait(uint32_t mbar, uint32_t phase)
{
    asm volatile(
        "{\n\t"
        ".reg .pred P;\n\t"
        "WL_%=:\n\t"
        "mbarrier.try_wait.parity.acquire.cta.shared::cta.b64 P, [%0], %1, 0x989680;\n\t"
        "@!P bra WL_%=;\n\t"
        "}" :: "r"(mbar), "r"(phase) : "memory");
}
__device__ __forceinline__ void st_async_f32(uint32_t rdst, float v, uint32_t rmbar)
{
    asm volatile(
        "st.async.weak.shared::cluster.mbarrier::complete_tx::bytes.b32 [%0], %1, [%2];"
        :: "r"(rdst), "r"(__float_as_uint(v)), "r"(rmbar) : "memory");
}

__device__ __forceinline__ unsigned long long pack2(float lo, float hi)
{
    unsigned long long u;
    asm("mov.b64 %0, {%1,%2};" : "=l"(u) : "f"(lo), "f"(hi));
    return u;
}
__device__ __forceinline__ float upadd(unsigned long long a)
{
    float lo, hi;
    asm("mov.b64 {%0,%1}, %2;" : "=f"(lo), "=f"(hi) : "l"(a));
    return lo + hi;
}
#define FMA2(acc, x, w) \
    asm("fma.rn.f32x2 %0, %1, %2, %0;" : "+l"(acc) : "l"(x), "l"(w))

__device__ __forceinline__ float tanha(float x)
{
    float y;
    asm("tanh.approx.f32 %0, %1;" : "=f"(y) : "f"(x));
    return y;
}
__device__ __forceinline__ float sigt(float x)
{
    return fmaf(0.5f, tanha(0.5f * x), 0.5f);
}

__global__ void __cluster_dims__(GRU_CLUSTER, 1, 1) __launch_bounds__(256, 1)
gru_kernel(const float* __restrict__ Wf,  const float* __restrict__ Whh,
           const float* __restrict__ bhh, const float* __restrict__ gia,
           const float* __restrict__ Wo,  const float* __restrict__ ob,
           float* __restrict__ out)
{
    __shared__ __align__(16) float sh[2][2][296];   // [batch][buf][rank slice @ r*36]
    __shared__ __align__(8)  unsigned long long mb[2][2];   // [batch][buf]

    unsigned r;
    asm("mov.u32 %0, %%cluster_ctarank;" : "=r"(r));
    int c  = blockIdx.x >> 3;      // cluster id 0..7
    int b0 = c * 2;
    int b1 = c * 2 + 1;
    int t  = threadIdx.x;
    int G  = t >> 3;
    int s  = t & 7;
    int j  = (int)r * 32 + G;
    int k0 = s * 32;

    // local barrier addresses + per-thread remote targets (rank s)
    uint32_t mbA0 = smem_u32(&mb[0][0]);
    uint32_t mbA1 = smem_u32(&mb[0][1]);
    uint32_t mbB0 = smem_u32(&mb[1][0]);
    uint32_t mbB1 = smem_u32(&mb[1][1]);
    uint32_t rmbA0  = mapa_u32(mbA0, s);
    uint32_t rmbA1  = mapa_u32(mbA1, s);
    uint32_t rmbB0  = mapa_u32(mbB0, s);
    uint32_t rmbB1  = mapa_u32(mbB1, s);
    uint32_t rdstA0 = mapa_u32(smem_u32(&sh[0][0][SPAD(j)]), s);
    uint32_t rdstA1 = mapa_u32(smem_u32(&sh[0][1][SPAD(j)]), s);
    uint32_t rdstB0 = mapa_u32(smem_u32(&sh[1][0][SPAD(j)]), s);
    uint32_t rdstB1 = mapa_u32(smem_u32(&sh[1][1][SPAD(j)]), s);

    // ---- packed register-resident weights (SHARED by both batches) ----
    unsigned long long wr[16], wz[16], wni[16], wnh[16], wo2[16];
#pragma unroll
    for (int i = 0; i < 16; i++) {
        int k = k0 + 2 * i;
        size_t rR = (size_t)j * 256 + k;
        size_t rZ = (size_t)(j + 256) * 256 + k;
        size_t rN = (size_t)(j + 512) * 256 + k;
        wr[i]  = pack2(Wf[rR] + Whh[rR], Wf[rR + 1] + Whh[rR + 1]);
        wz[i]  = pack2(Wf[rZ] + Whh[rZ], Wf[rZ + 1] + Whh[rZ + 1]);
        wni[i] = pack2(Wf[rN],           Wf[rN + 1]);
        wnh[i] = pack2(Whh[rN],          Whh[rN + 1]);
        wo2[i] = pack2(Wo[rR],           Wo[rR + 1]);
    }
    float br  = gia[16 * 768 + j]       + bhh[j];          // batch-independent
    float bz  = gia[16 * 768 + 256 + j] + bhh[256 + j];
    float bni = gia[16 * 768 + 512 + j];
    float bnh = bhh[512 + j];
    float bO  = ob[j];

    // ---- barrier init: 4 barriers, 256 arrivals/phase each ----
    if (t == 0) {
        mbar_init(mbA0, 256);
        mbar_init(mbA1, 256);
        mbar_init(mbB0, 256);
        mbar_init(mbB1, 256);
    }
    __syncthreads();
    mbar_expect_tx(mbA0, 4);
    mbar_expect_tx(mbA1, 4);
    mbar_expect_tx(mbB0, 4);
    mbar_expect_tx(mbB1, 4);
    cluster_sync_();

    // ---- peel step 0 for both batches: x = latent, h_{-1} = 0 ----
    float rA = sigt(gia[b0 * 768 + j] + bhh[j]);
    float zA = sigt(gia[b0 * 768 + 256 + j] + bhh[256 + j]);
    float hprevA = (1.f - zA) * tanha(gia[b0 * 768 + 512 + j] + rA * bhh[512 + j]);
    st_async_f32(rdstA0, hprevA, rmbA0);

    float rB = sigt(gia[b1 * 768 + j] + bhh[j]);
    float zB = sigt(gia[b1 * 768 + 256 + j] + bhh[256 + j]);
    float hprevB = (1.f - zB) * tanha(gia[b1 * 768 + 512 + j] + rB * bhh[512 + j]);
    st_async_f32(rdstB0, hprevB, rmbB0);

    float* outA = out + (size_t)b0 * TOTAL;
    float* outB = out + (size_t)b1 * TOTAL;
    int p = 0;
    int ph0 = 0, ph1 = 0;

    for (int n = 1; n < NCH; n++) {
        uint32_t phc = p ? (uint32_t)ph1 : (uint32_t)ph0;
        int q = p ^ 1;

        // ================= batch A =================
        {
            uint32_t mbc = p ? mbA1 : mbA0;
            mbar_wait(mbc, phc);
            mbar_expect_tx(mbc, 4);

            const float* cur = sh[0][p];
            unsigned long long ar = 0ull, az = 0ull, ani = 0ull, anh = 0ull, ao = 0ull;
#pragma unroll
            for (int i4 = 0; i4 < 8; i4++) {
                ulonglong2 uv = *reinterpret_cast<const ulonglong2*>(cur + s * 36 + i4 * 4);
                FMA2(ar,  uv.x, wr[2 * i4]);     FMA2(ar,  uv.y, wr[2 * i4 + 1]);
                FMA2(az,  uv.x, wz[2 * i4]);     FMA2(az,  uv.y, wz[2 * i4 + 1]);
                FMA2(ani, uv.x, wni[2 * i4]);    FMA2(ani, uv.y, wni[2 * i4 + 1]);
                FMA2(anh, uv.x, wnh[2 * i4]);    FMA2(anh, uv.y, wnh[2 * i4 + 1]);
                FMA2(ao,  uv.x, wo2[2 * i4]);    FMA2(ao,  uv.y, wo2[2 * i4 + 1]);
            }
            float vr  = upadd(ar);
            float vz  = upadd(az);
            float vni = upadd(ani);
            float vnh = upadd(anh);
#pragma unroll
            for (int m = 4; m >= 1; m >>= 1) {
                vr  += __shfl_xor_sync(0xffffffffu, vr,  m);
                vz  += __shfl_xor_sync(0xffffffffu, vz,  m);
                vni += __shfl_xor_sync(0xffffffffu, vni, m);
                vnh += __shfl_xor_sync(0xffffffffu, vnh, m);
            }
            float rg   = sigt(vr + br);
            float zg   = sigt(vz + bz);
            float ng   = tanha(vni + bni + rg * (vnh + bnh));
            float hnew = fmaf(zg, hprevA - ng, ng);
            hprevA = hnew;
            if (q == 0) st_async_f32(rdstA0, hnew, rmbA0);
            else        st_async_f32(rdstA1, hnew, rmbA1);

            float vo = upadd(ao);
#pragma unroll
            for (int m = 4; m >= 1; m >>= 1)
                vo += __shfl_xor_sync(0xffffffffu, vo, m);
            if (s == 0) outA[(size_t)(n - 1) * 256 + j] = vo + bO;
        }

        // ================= batch B =================
        {
            uint32_t mbc = p ? mbB1 : mbB0;
            mbar_wait(mbc, phc);
            mbar_expect_tx(mbc, 4);

            const float* cur = sh[1][p];
            unsigned long long ar = 0ull, az = 0ull, ani = 0ull, anh = 0ull, ao = 0ull;
#pragma unroll
            for (int i4 = 0; i4 < 8; i4++) {
                ulonglong2 uv = *reinterpret_cast<const ulonglong2*>(cur + s * 36 + i4 * 4);
                FMA2(ar,  uv.x, wr[2 * i4]);     FMA2(ar,  uv.y, wr[2 * i4 + 1]);
                FMA2(az,  uv.x, wz[2 * i4]);     FMA2(az,  uv.y, wz[2 * i4 + 1]);
                FMA2(ani, uv.x, wni[2 * i4]);    FMA2(ani, uv.y, wni[2 * i4 + 1]);
                FMA2(anh, uv.x, wnh[2 * i4]);    FMA2(anh, uv.y, wnh[2 * i4 + 1]);
                FMA2(ao,  uv.x, wo2[2 * i4]);    FMA2(ao,  uv.y, wo2[2 * i4 + 1]);
            }
            float vr  = upadd(ar);
            float vz  = upadd(az);
            float vni = upadd(ani);
            float vnh = upadd(anh);
#pragma unroll
            for (int m = 4; m >= 1; m >>= 1) {
                vr  += __shfl_xor_sync(0xffffffffu, vr,  m);
                vz  += __shfl_xor_sync(0xffffffffu, vz,  m);
                vni += __shfl_xor_sync(0xffffffffu, vni, m);
                vnh += __shfl_xor_sync(0xffffffffu, vnh, m);
            }
            float rg   = sigt(vr + br);
            float zg   = sigt(vz + bz);
            float ng   = tanha(vni + bni + rg * (vnh + bnh));
            float hnew = fmaf(zg, hprevB - ng, ng);
            hprevB = hnew;
            if (q == 0) st_async_f32(rdstB0, hnew, rmbB0);
            else        st_async_f32(rdstB1, hnew, rmbB1);

            float vo = upadd(ao);
#pragma unroll
            for (int m = 4; m >= 1; m >>= 1)
                vo += __shfl_xor_sync(0xffffffffu, vo, m);
            if (s == 0) outB[(size_t)(n - 1) * 256 + j] = vo + bO;
        }

        if (p) ph1 ^= 1; else ph0 ^= 1;
        p = q;
    }

    // ---- epilogue: chunk_1027 for both batches ----
    {
        uint32_t phc = p ? (uint32_t)ph1 : (uint32_t)ph0;
        mbar_wait(p ? mbA1 : mbA0, phc);
        const float* cur = sh[0][p];
        unsigned long long ao = 0ull;
#pragma unroll
        for (int i4 = 0; i4 < 8; i4++) {
            ulonglong2 uv = *reinterpret_cast<const ulonglong2*>(cur + s * 36 + i4 * 4);
            FMA2(ao, uv.x, wo2[2 * i4]);
            FMA2(ao, uv.y, wo2[2 * i4 + 1]);
        }
        float vo = upadd(ao);
#pragma unroll
        for (int m = 4; m >= 1; m >>= 1)
            vo += __shfl_xor_sync(0xffffffffu, vo, m);
        if (s == 0) outA[(size_t)1027 * 256 + j] = vo + bO;

        mbar_wait(p ? mbB1 : mbB0, phc);
        const float* curB = sh[1][p];
        unsigned long long aoB = 0ull;
#pragma unroll
        for (int i4 = 0; i4 < 8; i4++) {
            ulonglong2 uv = *reinterpret_cast<const ulonglong2*>(curB + s * 36 + i4 * 4);
            FMA2(aoB, uv.x, wo2[2 * i4]);
            FMA2(aoB, uv.y, wo2[2 * i4 + 1]);
        }
        float voB = upadd(aoB);
#pragma unroll
        for (int m = 4; m >= 1; m >>= 1)
            voB += __shfl_xor_sync(0xffffffffu, voB, m);
        if (s == 0) outB[(size_t)1027 * 256 + j] = voB + bO;
    }
    cluster_sync_();   // keep SMEM alive until all in-flight st.asyncs drain
}

// =====================================================================
// launch
// =====================================================================
extern "C" void kernel_launch(void* const* d_in, const int* in_sizes, int n_in,
                              void* d_out, int out_size)
{
    const float* genome  = (const float*)d_in[0];
    const float* embedW  = (const float*)d_in[1];
    const float* embedB  = (const float*)d_in[2];
    const float* qkvW    = (const float*)d_in[3];
    const float* qkvB    = (const float*)d_in[4];
    const float* projW   = (const float*)d_in[5];
    const float* projB   = (const float*)d_in[6];
    const float* ln1g    = (const float*)d_in[7];
    const float* ln1b    = (const float*)d_in[8];
    const float* ln2g    = (const float*)d_in[9];
    const float* ln2b    = (const float*)d_in[10];
    const float* W1      = (const float*)d_in[11];
    const float* B1      = (const float*)d_in[12];
    const float* W2      = (const float*)d_in[13];
    const float* B2      = (const float*)d_in[14];
    const float* gWih    = (const float*)d_in[15];
    const float* gWhh    = (const float*)d_in[16];
    const float* gbih    = (const float*)d_in[17];
    const float* gbhh    = (const float*)d_in[18];
    const float* oW      = (const float*)d_in[19];
    const float* oB      = (const float*)d_in[20];
    float* out = (float*)d_out;

    float *p_h, *p_qkv, *p_attn, *p_tmp, *p_ffn, *p_lat, *p_wf, *p_gia;
    cudaGetSymbolAddress((void**)&p_h,    g_h);
    cudaGetSymbolAddress((void**)&p_qkv,  g_qkv);
    cudaGetSymbolAddress((void**)&p_attn, g_attn);
    cudaGetSymbolAddress((void**)&p_tmp,  g_tmp);
    cudaGetSymbolAddress((void**)&p_ffn,  g_ffn);
    cudaGetSymbolAddress((void**)&p_lat,  g_latent);
    cudaGetSymbolAddress((void**)&p_wf,   g_wf);
    cudaGetSymbolAddress((void**)&p_gia,  g_gia);

    fuse_kernel<<<192, 256>>>(gWih, oW, p_wf);

    embed_kernel<<<BATCH * GL, Hdim>>>(genome, embedW, embedB, p_h);

    for (int l = 0; l < NLAY; l++) {
        gemm_rows4<3 * Hdim, Hdim, false><<<64, 3 * Hdim>>>(
            p_h, qkvW + (size_t)l * 3 * Hdim * Hdim, qkvB + l * 3 * Hdim, p_qkv);
        attn_kernel<<<BATCH * NH, 256>>>(p_qkv, p_attn);
        gemm_rows4<Hdim, Hdim, false><<<64, Hdim>>>(
            p_attn, projW + (size_t)l * Hdim * Hdim, projB + l * Hdim, p_tmp);
        addln_kernel<<<BATCH * GL, Hdim>>>(p_tmp, p_h, ln1g + l * Hdim, ln1b + l * Hdim);
        gemm_rows4<4 * Hdim, Hdim, true><<<64, 4 * Hdim>>>(
            p_h, W1 + (size_t)l * 4 * Hdim * Hdim, B1 + l * 4 * Hdim, p_ffn);
        gemm_rows4<Hdim, 4 * Hdim, false><<<64, Hdim>>>(
            p_ffn, W2 + (size_t)l * 4 * Hdim * Hdim, B2 + l * Hdim, p_tmp);
        addln_kernel<<<BATCH * GL, Hdim>>>(p_tmp, p_h, ln2g + l * Hdim, ln2b + l * Hdim);
    }

    latent_kernel<<<BATCH, Hdim>>>(p_h, p_lat);
    gia_kernel<<<768, 32>>>(gWih, gbih, p_lat, oB, p_gia);

    // 8 clusters x 8 CTAs, 2 batches per cluster
    gru_kernel<<<(BATCH / 2) * GRU_CLUSTER, 256>>>(p_wf, gWhh, gbhh, p_gia, oW, oB, out);
}